// round 12
// baseline (speedup 1.0000x reference)
#include <cuda_runtime.h>
#include <cstdint>

#define NPAD  8192
#define TSZ   512                  // elements per tile side
#define TREC  (TSZ / 2)            // 256 records per side
#define PAN   (NPAD / TSZ)         // 16 panels
#define NB    (PAN * (PAN + 1) / 2)  // 136 blocks (triangle of tiles)
#define NT    1024
#define NWARP 32

#define PACKF2(r, lo, hi)   asm("mov.b64 %0, {%1, %2};" : "=l"(r) : "f"(lo), "f"(hi))
#define UNPACKF2(lo, hi, x) asm("mov.b64 {%0, %1}, %2;" : "=f"(lo), "=f"(hi) : "l"(x))
#define FMAF2(r, a, b, c)   asm("fma.rn.f32x2 %0, %1, %2, %3;" : "=l"(r) : "l"(a), "l"(b), "l"(c))

__device__ float        g_vpart[NB];        // per-block |z| partials (distinct addrs)
__device__ float        g_spart[5][PAN];    // sp, st, spt, src, cnt per diagonal tile
__device__ unsigned int g_done = 0;

__global__ __launch_bounds__(NT, 1)
void cindex_kernel(const float* __restrict__ pred,
                   const float* __restrict__ gt,
                   const int* __restrict__ ft_idx,
                   const int* __restrict__ fm_idx,
                   float* __restrict__ out, int n)
{
    // record r (2 elements) = 16B: { -p0, -p1, t0, t1 }  (masked values)
    __shared__ float rowf[TREC * 4];
    __shared__ float colf[TREC * 4];
    __shared__ float red[6][NWARP];

    const int tid  = threadIdx.x;
    const int lane = tid & 31;
    const int wid  = tid >> 5;
    const int fmi  = fm_idx[0];
    const int fti  = ft_idx[0];

    // ---- tile coordinates (a, b), a <= b ----
    int a = 0, acc = 0;
    {
        int bid = blockIdx.x;
        while (bid >= acc + (PAN - a)) { acc += PAN - a; ++a; }
    }
    const int  b    = a + ((int)blockIdx.x - acc);
    const bool diag = (a == b);

    // ---- Phase A: stage row tile (threads 0..511) / col tile (512..1023) ----
    float sp = 0.f, st = 0.f, spt = 0.f, src = 0.f, cnt = 0.f;
    {
        const int half = tid >> 9;              // 0 = rows (tile a), 1 = cols (tile b)
        const int t    = tid & 511;
        const int e    = (half ? b : a) * TSZ + t;
        float mp = 0.f, mt = 0.f;
        if (e < n) {
            float2 g = ((const float2*)gt)[e];
            float w  = fmi ? g.y : g.x;
            float tv = fti ? g.y : g.x;
            if (w == 1.0f) {
                float pv = pred[e];
                mp = -pv; mt = tv;
                if (half == 0 && diag) {        // diag tiles own the elementwise sums
                    float c = pv * tv;
                    sp += pv; st += tv; spt += c;
                    src += fmaxf(c, 0.f); cnt += 1.f;
                }
            }
        }
        float* dst = half ? colf : rowf;
        dst[(t >> 1) * 4 +     (t & 1)] = mp;
        dst[(t >> 1) * 4 + 2 + (t & 1)] = mt;
    }
    __syncthreads();

    // ---- Phase B: 512x512 tile; warp (wr, wc) = 128 rows x 32 records ----
    float v;
    {
        const int wr = wid >> 3;                // 0..3
        const int wc = wid & 7;                 // 0..7
        const float4*     rowq = (const float4*)rowf;
        const ulonglong2* colv = (const ulonglong2*)colf;
        uint64_t one2, mone2, zero2;
        PACKF2(one2, 1.0f, 1.0f);
        PACKF2(mone2, -1.0f, -1.0f);
        PACKF2(zero2, 0.0f, 0.0f);

        const int rbase = 64 * wr + 2 * lane;   // lane's 4 rows (2 records)
        float4 ra = rowq[rbase];
        float4 rb = rowq[rbase + 1];
        uint64_t pi2[4], ti2[4];
        PACKF2(pi2[0], -ra.x, -ra.x); PACKF2(ti2[0], ra.z, ra.z);
        PACKF2(pi2[1], -ra.y, -ra.y); PACKF2(ti2[1], ra.w, ra.w);
        PACKF2(pi2[2], -rb.x, -rb.x); PACKF2(ti2[2], rb.z, rb.z);
        PACKF2(pi2[3], -rb.y, -rb.y); PACKF2(ti2[3], rb.w, rb.w);

        float aL[4] = {0, 0, 0, 0}, aH[4] = {0, 0, 0, 0};
        const int k0 = 32 * wc;
        #pragma unroll 4
        for (int k = k0; k < k0 + 32; ++k) {
            ulonglong2 va = colv[k];            // broadcast LDS.128
            #pragma unroll
            for (int r = 0; r < 4; ++r) {
                uint64_t dp2, dt2, x2;
                FMAF2(dp2, pi2[r], one2, va.x); // pi - pj
                FMAF2(dt2, va.y, mone2, ti2[r]);// ti - tj
                FMAF2(x2, dp2, dt2, zero2);     // dp * dt
                float xl, xh;
                UNPACKF2(xl, xh, x2);
                aL[r] += fabsf(xl);
                aH[r] += fabsf(xh);
            }
        }
        float s = (aL[0] + aH[0]) + (aL[1] + aH[1])
                + (aL[2] + aH[2]) + (aL[3] + aH[3]);
        v = diag ? 0.5f * s : s;                // diag square counts pairs twice
    }

    // ---- Phase C: deterministic block reduce of {v, sp, st, spt, src, cnt} ----
    float vals[6] = {v, sp, st, spt, src, cnt};
    #pragma unroll
    for (int j = 0; j < 6; ++j) {
        #pragma unroll
        for (int o = 16; o > 0; o >>= 1)
            vals[j] += __shfl_down_sync(0xffffffffu, vals[j], o);
        if (lane == 0) red[j][wid] = vals[j];
    }
    __syncthreads();
    if (wid == 0) {
        float t6[6];
        #pragma unroll
        for (int j = 0; j < 6; ++j) {
            t6[j] = red[j][lane];
            #pragma unroll
            for (int o = 16; o > 0; o >>= 1)
                t6[j] += __shfl_down_sync(0xffffffffu, t6[j], o);
        }

        unsigned rank = 0;
        if (lane == 0) {
            g_vpart[blockIdx.x] = t6[0];
            if (diag) {
                g_spart[0][a] = t6[1]; g_spart[1][a] = t6[2];
                g_spart[2][a] = t6[3]; g_spart[3][a] = t6[4];
                g_spart[4][a] = t6[5];
            }
            __threadfence();
            rank = atomicAdd(&g_done, 1u);
        }
        rank = __shfl_sync(0xffffffffu, rank, 0);

        if (rank == (unsigned)(gridDim.x - 1)) {     // last block finalizes
            __threadfence();
            double s = 0.0;
            for (int i = lane; i < NB; i += 32)
                s += (double)__ldcg(&g_vpart[i]);
            #pragma unroll
            for (int o = 16; o > 0; o >>= 1)
                s += __shfl_down_sync(0xffffffffu, s, o);

            double t5[5];
            #pragma unroll
            for (int j = 0; j < 5; ++j) {
                double u = (lane < PAN) ? (double)__ldcg(&g_spart[j][lane]) : 0.0;
                #pragma unroll
                for (int o = 16; o > 0; o >>= 1)
                    u += __shfl_down_sync(0xffffffffu, u, o);
                t5[j] = u;
            }

            if (lane == 0) {
                double absum = s;                    // Σ|z'| over unordered pairs
                double m  = t5[4];
                double Sz = (double)NPAD * t5[2] - t5[0] * t5[1];
                double Rp = 0.5 * (Sz + absum);
                double target = Rp - ((double)NPAD - m) * t5[3];
                float res = 0.0f;
                if (m > 1.5)
                    res = (float)(target / (50.0 * m * (m - 1.0)));
                out[0] = res;
                g_done = 0u;                         // self-clean for next call
            }
        }
    }
}

extern "C" void kernel_launch(void* const* d_in, const int* in_sizes, int n_in,
                              void* d_out, int out_size) {
    const float* pred = (const float*)d_in[0];
    const float* gt   = (const float*)d_in[1];
    const int* ft     = (const int*)d_in[2];
    const int* fm     = (const int*)d_in[3];
    float* out        = (float*)d_out;
    const int n = in_sizes[0];

    cindex_kernel<<<NB, NT>>>(pred, gt, ft, fm, out, n);
}